// round 15
// baseline (speedup 1.0000x reference)
#include <cuda_runtime.h>
#include <cuda_fp16.h>
#include <cuda_bf16.h>

#define NUM_USERS 100000
#define NUM_ITEMS 50000
#define DIM 64
#define N_TOTAL (NUM_USERS + NUM_ITEMS)
#define NNZ 4800000
#define TOT (N_TOTAL * DIM)

#define SCAN_CHUNK 1024
#define NCHUNK ((N_TOTAL + SCAN_CHUNK - 1) / SCAN_CHUNK)   // 147
#define GRID_ELEM ((TOT / 4 + 255) / 256)                   // 9375
#define GRID_EDGE ((NNZ + 255) / 256)                       // 18750

// fp16 layer embeddings (gather operands AND epilogue inputs)
__device__ __align__(16) __half g_h0[TOT];
__device__ __align__(16) __half g_h1[TOT];
__device__ __align__(16) __half g_h2[TOT];

// CSR build scratch
__device__ int g_cnt[N_TOTAL];            // zero at load; re-zeroed by lg_scan each call
__device__ int g_rowptr[N_TOTAL + 1];
__device__ int g_ofs[N_TOTAL];
__device__ unsigned long long g_state[NCHUNK];  // decoupled-lookback state
__device__ __align__(8) int2 g_cv[NNZ];   // .x = row-byte-offset (col*128), .y = val bits

// ---------------------------------------------------------------------------
// fused init + hist (independent; grid-partitioned)
// ---------------------------------------------------------------------------
__global__ void __launch_bounds__(256) lg_init_hist(const float* __restrict__ ue,
                                                    const float* __restrict__ ie,
                                                    const int* __restrict__ rows) {
    if (blockIdx.x < GRID_ELEM) {
        int i = blockIdx.x * blockDim.x + threadIdx.x;
        if (blockIdx.x == 0 && threadIdx.x < NCHUNK) g_state[threadIdx.x] = 0ULL;
        if (i >= TOT / 4) return;
        const int user4 = (NUM_USERS * DIM) / 4;
        float4 v = (i < user4) ? __ldg((const float4*)ue + i)
                               : __ldg((const float4*)ie + (i - user4));
        __half2 h01 = __float22half2_rn(make_float2(v.x, v.y));
        __half2 h23 = __float22half2_rn(make_float2(v.z, v.w));
        uint2 packed = make_uint2(*(unsigned*)&h01, *(unsigned*)&h23);
        ((uint2*)g_h0)[i] = packed;
    } else {
        int e = (blockIdx.x - GRID_ELEM) * blockDim.x + threadIdx.x;
        if (e >= NNZ) return;
        atomicAdd(&g_cnt[__ldcs(rows + e)], 1);
    }
}

// ---------------------------------------------------------------------------
// Single-kernel exclusive scan (decoupled lookback, one wave on 148 SMs).
// Re-zeroes g_cnt for the next call.
// ---------------------------------------------------------------------------
__global__ void __launch_bounds__(SCAN_CHUNK) lg_scan() {
    __shared__ int ws[32];
    __shared__ int s_excl;
    const int bid = blockIdx.x;
    const int tid = threadIdx.x, lane = tid & 31, w = tid >> 5;
    const int i = bid * SCAN_CHUNK + tid;

    int v = (i < N_TOTAL) ? g_cnt[i] : 0;
    if (i < N_TOTAL) g_cnt[i] = 0;

    int inc = v;
    #pragma unroll
    for (int d = 1; d < 32; d <<= 1) {
        int t = __shfl_up_sync(0xffffffffu, inc, d);
        if (lane >= d) inc += t;
    }
    if (lane == 31) ws[w] = inc;
    __syncthreads();
    if (w == 0) {
        int s = ws[lane];
        #pragma unroll
        for (int d = 1; d < 32; d <<= 1) {
            int t = __shfl_up_sync(0xffffffffu, s, d);
            if (lane >= d) s += t;
        }
        ws[lane] = s;
    }
    __syncthreads();
    int total = ws[31];

    if (w == 0) {
        if (bid == 0) {
            if (lane == 0) {
                s_excl = 0;
                atomicExch(&g_state[0], (2ULL << 32) | (unsigned)total);
            }
        } else {
            if (lane == 0)
                atomicExch(&g_state[bid], (1ULL << 32) | (unsigned)total);
            int run = 0;
            int j = bid - 1;
            for (;;) {
                int idx = j - lane;
                unsigned long long st = (idx >= 0)
                    ? atomicAdd(&g_state[idx], 0ULL)
                    : (2ULL << 32);
                unsigned status = (unsigned)(st >> 32);
                if (__any_sync(0xffffffffu, status == 0)) continue;
                unsigned mask2 = __ballot_sync(0xffffffffu, status == 2);
                if (mask2) {
                    int firstLane = __ffs(mask2) - 1;
                    int contrib = (lane <= firstLane) ? (int)(unsigned)st : 0;
                    #pragma unroll
                    for (int d = 16; d > 0; d >>= 1)
                        contrib += __shfl_down_sync(0xffffffffu, contrib, d);
                    contrib = __shfl_sync(0xffffffffu, contrib, 0);
                    run += contrib;
                    break;
                } else {
                    int contrib = (int)(unsigned)st;
                    #pragma unroll
                    for (int d = 16; d > 0; d >>= 1)
                        contrib += __shfl_down_sync(0xffffffffu, contrib, d);
                    contrib = __shfl_sync(0xffffffffu, contrib, 0);
                    run += contrib;
                    j -= 32;
                }
            }
            if (lane == 0) {
                s_excl = run;
                atomicExch(&g_state[bid], (2ULL << 32) | (unsigned)(run + total));
            }
        }
    }
    __syncthreads();

    int excl = inc - v + (w > 0 ? ws[w - 1] : 0) + s_excl;
    if (i < N_TOTAL) { g_rowptr[i] = excl; g_ofs[i] = excl; }
    if (bid == 0 && tid == 0) g_rowptr[N_TOTAL] = NNZ;
}

// ---------------------------------------------------------------------------
// scatter: 4 edges per thread (int4 streamed loads; MLP=4 on the ATOMG+STG
// chain). cv.x stores the row BYTE OFFSET (col * 128).
// ---------------------------------------------------------------------------
__global__ void __launch_bounds__(256) lg_scatter(const int* __restrict__ rows,
                                                  const int* __restrict__ cols,
                                                  const float* __restrict__ vals) {
    int t = blockIdx.x * blockDim.x + threadIdx.x;
    if (t >= NNZ / 4) return;
    int4 r = __ldcs((const int4*)rows + t);
    int4 c = __ldcs((const int4*)cols + t);
    int4 v = __ldcs((const int4*)vals + t);   // raw fp32 bits
    int p0 = atomicAdd(&g_ofs[r.x], 1);
    int p1 = atomicAdd(&g_ofs[r.y], 1);
    int p2 = atomicAdd(&g_ofs[r.z], 1);
    int p3 = atomicAdd(&g_ofs[r.w], 1);
    __stcs(&g_cv[p0], make_int2(c.x << 7, v.x));
    __stcs(&g_cv[p1], make_int2(c.y << 7, v.y));
    __stcs(&g_cv[p2], make_int2(c.z << 7, v.z));
    __stcs(&g_cv[p3], make_int2(c.w << 7, v.w));
}

// ---------------------------------------------------------------------------
// CSR SpMM core, quarter-warp scheme (R13 layout: coalesced lane-staged cv
// loads + SHFL extraction — measured best) with two additions:
//   * packed fma.rn.f32x2 accumulate (half the FMA issue slots)
//   * software-pipelined cv load (next chunk's metadata prefetched while the
//     current chunk's 8 gather groups execute)
// Quarter q (8 lanes) handles edge 4g+q of each group; a lane gathers one
// uint4 (16B = 8 halves) of the edge's x row.
// ---------------------------------------------------------------------------
__device__ __forceinline__ void q_accum2(const char* __restrict__ xb,
                                         int ofs, int vbits,
                                         unsigned long long* acc) {
    uint4 xv = __ldg((const uint4*)(xb + ofs));
    unsigned long long vv;
    asm("mov.b64 %0, {%1, %1};" : "=l"(vv) : "r"(vbits));
    float2 f0 = __half22float2(*(const __half2*)&xv.x);
    float2 f1 = __half22float2(*(const __half2*)&xv.y);
    float2 f2 = __half22float2(*(const __half2*)&xv.z);
    float2 f3 = __half22float2(*(const __half2*)&xv.w);
    unsigned long long u0, u1, u2, u3;
    asm("mov.b64 %0, {%1, %2};" : "=l"(u0) : "f"(f0.x), "f"(f0.y));
    asm("mov.b64 %0, {%1, %2};" : "=l"(u1) : "f"(f1.x), "f"(f1.y));
    asm("mov.b64 %0, {%1, %2};" : "=l"(u2) : "f"(f2.x), "f"(f2.y));
    asm("mov.b64 %0, {%1, %2};" : "=l"(u3) : "f"(f3.x), "f"(f3.y));
    asm("fma.rn.f32x2 %0, %1, %2, %0;" : "+l"(acc[0]) : "l"(vv), "l"(u0));
    asm("fma.rn.f32x2 %0, %1, %2, %0;" : "+l"(acc[1]) : "l"(vv), "l"(u1));
    asm("fma.rn.f32x2 %0, %1, %2, %0;" : "+l"(acc[2]) : "l"(vv), "l"(u2));
    asm("fma.rn.f32x2 %0, %1, %2, %0;" : "+l"(acc[3]) : "l"(vv), "l"(u3));
}

__device__ __forceinline__ void spmm_row(const char* __restrict__ xb,
                                         int beg, int end, int lane,
                                         float* a /* out[8] */) {
    const int q = lane >> 3;     // quarter id: which edge of each 4-group
    unsigned long long acc[4] = {0ULL, 0ULL, 0ULL, 0ULL};

    int deg = end - beg;
    int full_end = beg + (deg & ~31);

    // software-pipelined full chunks: coalesced cv load (1 LDG.64/lane),
    // SHFL extraction, 8 gather groups per chunk
    if (beg < full_end) {
        int2 ed = __ldcs(g_cv + beg + lane);
        for (int j = beg + 32; j < full_end; j += 32) {
            int2 ed_next = __ldcs(g_cv + j + lane);
            #pragma unroll
            for (int g = 0; g < 8; g++) {
                int src = 4 * g + q;
                int o = __shfl_sync(0xffffffffu, ed.x, src);
                int b = __shfl_sync(0xffffffffu, ed.y, src);
                q_accum2(xb, o, b, acc);
            }
            ed = ed_next;
        }
        #pragma unroll
        for (int g = 0; g < 8; g++) {
            int src = 4 * g + q;
            int o = __shfl_sync(0xffffffffu, ed.x, src);
            int b = __shfl_sync(0xffffffffu, ed.y, src);
            q_accum2(xb, o, b, acc);
        }
    }

    // partial tail chunk: predicated groups (vbits=0 => no-op accumulate)
    int m = end - full_end;
    if (m > 0) {
        int jj = full_end + lane;
        int2 ed = (jj < end) ? __ldcs(g_cv + jj) : make_int2(0, 0);
        int groups = (m + 3) >> 2;
        #pragma unroll
        for (int g = 0; g < 8; g++) {
            if (g >= groups) break;
            int src = 4 * g + q;
            int o = __shfl_sync(0xffffffffu, ed.x, src);
            int b = __shfl_sync(0xffffffffu, ed.y, src);
            bool ok = (src < m);
            q_accum2(xb, ok ? o : 0, ok ? b : 0, acc);
        }
    }

    // unpack b64 accumulators to floats
    #pragma unroll
    for (int k = 0; k < 4; k++) {
        unsigned lo, hi;
        asm("mov.b64 {%0, %1}, %2;" : "=r"(lo), "=r"(hi) : "l"(acc[k]));
        a[2 * k]     = __int_as_float(lo);
        a[2 * k + 1] = __int_as_float(hi);
    }
    // reduce the 4 quarter-warps (same output row, different edges)
    #pragma unroll
    for (int k = 0; k < 8; k++) {
        a[k] += __shfl_xor_sync(0xffffffffu, a[k], 8);
        a[k] += __shfl_xor_sync(0xffffffffu, a[k], 16);
    }
}

// yh = fp16(A @ x), x fp16.  40-reg cap (6 blocks/SM) — measured best.
__global__ void __launch_bounds__(256, 6) lg_csr_spmm(const __half* __restrict__ xh,
                                                      uint4* __restrict__ yh16) {
    int gtid = blockIdx.x * blockDim.x + threadIdx.x;
    int row  = gtid >> 5;
    int lane = gtid & 31;
    if (row >= N_TOTAL) return;
    int beg = __ldg(g_rowptr + row);
    int end = __ldg(g_rowptr + row + 1);
    const char* xb = (const char*)xh + (lane & 7) * 16;
    float a[8];
    spmm_row(xb, beg, end, lane, a);
    if (lane < 8) {
        __half2 p0 = __float22half2_rn(make_float2(a[0], a[1]));
        __half2 p1 = __float22half2_rn(make_float2(a[2], a[3]));
        __half2 p2 = __float22half2_rn(make_float2(a[4], a[5]));
        __half2 p3 = __float22half2_rn(make_float2(a[6], a[7]));
        uint4 pk = make_uint4(*(unsigned*)&p0, *(unsigned*)&p1,
                              *(unsigned*)&p2, *(unsigned*)&p3);
        yh16[(size_t)row * 8 + lane] = pk;
    }
}

// Layer 3 fused with the mean: out = 0.25 * (h0 + h1 + h2 + A@h2).
// NO min-blocks clamp here (R12 showed it spills and costs ~19 us).
__global__ void __launch_bounds__(256) lg_csr_spmm_final(float* __restrict__ out) {
    int gtid = blockIdx.x * blockDim.x + threadIdx.x;
    int row  = gtid >> 5;
    int lane = gtid & 31;
    if (row >= N_TOTAL) return;
    int beg = __ldg(g_rowptr + row);
    int end = __ldg(g_rowptr + row + 1);
    const char* xb = (const char*)g_h2 + (lane & 7) * 16;
    float a[8];
    spmm_row(xb, beg, end, lane, a);
    if (lane < 8) {
        size_t p = (size_t)row * 8 + lane;
        uint4 u0 = __ldg((const uint4*)g_h0 + p);
        uint4 u1 = __ldg((const uint4*)g_h1 + p);
        uint4 u2 = __ldg((const uint4*)g_h2 + p);
        float o[8];
        const unsigned* pu0 = &u0.x;
        const unsigned* pu1 = &u1.x;
        const unsigned* pu2 = &u2.x;
        #pragma unroll
        for (int k = 0; k < 4; k++) {
            float2 e0 = __half22float2(*(const __half2*)&pu0[k]);
            float2 e1 = __half22float2(*(const __half2*)&pu1[k]);
            float2 e2 = __half22float2(*(const __half2*)&pu2[k]);
            o[2*k]   = (e0.x + e1.x + e2.x + a[2*k])   * 0.25f;
            o[2*k+1] = (e0.y + e1.y + e2.y + a[2*k+1]) * 0.25f;
        }
        float4* dst = (float4*)(out + (size_t)row * DIM + lane * 8);
        dst[0] = make_float4(o[0], o[1], o[2], o[3]);
        dst[1] = make_float4(o[4], o[5], o[6], o[7]);
    }
}

extern "C" void kernel_launch(void* const* d_in, const int* in_sizes, int n_in,
                              void* d_out, int out_size) {
    const float* ue   = (const float*)d_in[0];
    const float* ie   = (const float*)d_in[1];
    const float* vals = (const float*)d_in[2];
    const int*   rows = (const int*)  d_in[3];
    const int*   cols = (const int*)  d_in[4];
    float* out = (float*)d_out;

    __half *h0, *h1, *h2;
    cudaGetSymbolAddress((void**)&h0, g_h0);
    cudaGetSymbolAddress((void**)&h1, g_h1);
    cudaGetSymbolAddress((void**)&h2, g_h2);

    const int TPB = 256;
    const int grid_rows = (N_TOTAL * 32 + TPB - 1) / TPB;

    lg_init_hist<<<GRID_ELEM + GRID_EDGE, TPB>>>(ue, ie, rows);
    lg_scan     <<<NCHUNK, SCAN_CHUNK>>>();
    lg_scatter  <<<(NNZ / 4 + TPB - 1) / TPB, TPB>>>(rows, cols, vals);

    lg_csr_spmm      <<<grid_rows, TPB>>>(h0, (uint4*)h1);
    lg_csr_spmm      <<<grid_rows, TPB>>>(h1, (uint4*)h2);
    lg_csr_spmm_final<<<grid_rows, TPB>>>(out);
}

// round 16
// speedup vs baseline: 1.1481x; 1.1481x over previous
#include <cuda_runtime.h>
#include <cuda_fp16.h>
#include <cuda_bf16.h>

#define NUM_USERS 100000
#define NUM_ITEMS 50000
#define DIM 64
#define N_TOTAL (NUM_USERS + NUM_ITEMS)
#define NNZ 4800000
#define TOT (N_TOTAL * DIM)

#define SCAN_CHUNK 1024
#define NCHUNK ((N_TOTAL + SCAN_CHUNK - 1) / SCAN_CHUNK)   // 147
#define GRID_ELEM ((TOT / 4 + 255) / 256)                   // 9375
#define GRID_EDGE4 ((NNZ / 4 + 255) / 256)                  // 4688 (4 edges/thread)

// fp16 layer embeddings (gather operands AND epilogue inputs)
__device__ __align__(16) __half g_h0[TOT];
__device__ __align__(16) __half g_h1[TOT];
__device__ __align__(16) __half g_h2[TOT];

// CSR build scratch
__device__ int g_cnt[N_TOTAL];            // zero at load; re-zeroed by lg_scan each call
__device__ int g_rowptr[N_TOTAL + 1];
__device__ int g_ofs[N_TOTAL];
__device__ unsigned long long g_state[NCHUNK];  // decoupled-lookback state
__device__ __align__(8) int2 g_cv[NNZ];   // .x = row-byte-offset (col*128), .y = val bits

// ---------------------------------------------------------------------------
// fused init + hist (independent; grid-partitioned). Hist half processes
// 4 edges/thread via int4 loads (MLP=4 on the spread atomics).
// ---------------------------------------------------------------------------
__global__ void __launch_bounds__(256) lg_init_hist(const float* __restrict__ ue,
                                                    const float* __restrict__ ie,
                                                    const int* __restrict__ rows) {
    if (blockIdx.x < GRID_ELEM) {
        int i = blockIdx.x * blockDim.x + threadIdx.x;
        if (blockIdx.x == 0 && threadIdx.x < NCHUNK) g_state[threadIdx.x] = 0ULL;
        if (i >= TOT / 4) return;
        const int user4 = (NUM_USERS * DIM) / 4;
        float4 v = (i < user4) ? __ldg((const float4*)ue + i)
                               : __ldg((const float4*)ie + (i - user4));
        __half2 h01 = __float22half2_rn(make_float2(v.x, v.y));
        __half2 h23 = __float22half2_rn(make_float2(v.z, v.w));
        uint2 packed = make_uint2(*(unsigned*)&h01, *(unsigned*)&h23);
        ((uint2*)g_h0)[i] = packed;
    } else {
        int t = (blockIdx.x - GRID_ELEM) * blockDim.x + threadIdx.x;
        if (t >= NNZ / 4) return;
        int4 r = __ldcs((const int4*)rows + t);
        atomicAdd(&g_cnt[r.x], 1);
        atomicAdd(&g_cnt[r.y], 1);
        atomicAdd(&g_cnt[r.z], 1);
        atomicAdd(&g_cnt[r.w], 1);
    }
}

// ---------------------------------------------------------------------------
// Single-kernel exclusive scan (decoupled lookback, one wave on 148 SMs).
// Re-zeroes g_cnt for the next call.
// ---------------------------------------------------------------------------
__global__ void __launch_bounds__(SCAN_CHUNK) lg_scan() {
    __shared__ int ws[32];
    __shared__ int s_excl;
    const int bid = blockIdx.x;
    const int tid = threadIdx.x, lane = tid & 31, w = tid >> 5;
    const int i = bid * SCAN_CHUNK + tid;

    int v = (i < N_TOTAL) ? g_cnt[i] : 0;
    if (i < N_TOTAL) g_cnt[i] = 0;

    int inc = v;
    #pragma unroll
    for (int d = 1; d < 32; d <<= 1) {
        int t = __shfl_up_sync(0xffffffffu, inc, d);
        if (lane >= d) inc += t;
    }
    if (lane == 31) ws[w] = inc;
    __syncthreads();
    if (w == 0) {
        int s = ws[lane];
        #pragma unroll
        for (int d = 1; d < 32; d <<= 1) {
            int t = __shfl_up_sync(0xffffffffu, s, d);
            if (lane >= d) s += t;
        }
        ws[lane] = s;
    }
    __syncthreads();
    int total = ws[31];

    if (w == 0) {
        if (bid == 0) {
            if (lane == 0) {
                s_excl = 0;
                atomicExch(&g_state[0], (2ULL << 32) | (unsigned)total);
            }
        } else {
            if (lane == 0)
                atomicExch(&g_state[bid], (1ULL << 32) | (unsigned)total);
            int run = 0;
            int j = bid - 1;
            for (;;) {
                int idx = j - lane;
                unsigned long long st = (idx >= 0)
                    ? atomicAdd(&g_state[idx], 0ULL)
                    : (2ULL << 32);
                unsigned status = (unsigned)(st >> 32);
                if (__any_sync(0xffffffffu, status == 0)) continue;
                unsigned mask2 = __ballot_sync(0xffffffffu, status == 2);
                if (mask2) {
                    int firstLane = __ffs(mask2) - 1;
                    int contrib = (lane <= firstLane) ? (int)(unsigned)st : 0;
                    #pragma unroll
                    for (int d = 16; d > 0; d >>= 1)
                        contrib += __shfl_down_sync(0xffffffffu, contrib, d);
                    contrib = __shfl_sync(0xffffffffu, contrib, 0);
                    run += contrib;
                    break;
                } else {
                    int contrib = (int)(unsigned)st;
                    #pragma unroll
                    for (int d = 16; d > 0; d >>= 1)
                        contrib += __shfl_down_sync(0xffffffffu, contrib, d);
                    contrib = __shfl_sync(0xffffffffu, contrib, 0);
                    run += contrib;
                    j -= 32;
                }
            }
            if (lane == 0) {
                s_excl = run;
                atomicExch(&g_state[bid], (2ULL << 32) | (unsigned)(run + total));
            }
        }
    }
    __syncthreads();

    int excl = inc - v + (w > 0 ? ws[w - 1] : 0) + s_excl;
    if (i < N_TOTAL) { g_rowptr[i] = excl; g_ofs[i] = excl; }
    if (bid == 0 && tid == 0) g_rowptr[N_TOTAL] = NNZ;
}

// ---------------------------------------------------------------------------
// scatter: 4 edges per thread (int4 streamed loads; MLP=4 on the ATOMG+STG
// chain). cv.x stores the row BYTE OFFSET (col * 128).
// ---------------------------------------------------------------------------
__global__ void __launch_bounds__(256) lg_scatter(const int* __restrict__ rows,
                                                  const int* __restrict__ cols,
                                                  const float* __restrict__ vals) {
    int t = blockIdx.x * blockDim.x + threadIdx.x;
    if (t >= NNZ / 4) return;
    int4 r = __ldcs((const int4*)rows + t);
    int4 c = __ldcs((const int4*)cols + t);
    int4 v = __ldcs((const int4*)vals + t);   // raw fp32 bits
    int p0 = atomicAdd(&g_ofs[r.x], 1);
    int p1 = atomicAdd(&g_ofs[r.y], 1);
    int p2 = atomicAdd(&g_ofs[r.z], 1);
    int p3 = atomicAdd(&g_ofs[r.w], 1);
    __stcs(&g_cv[p0], make_int2(c.x << 7, v.x));
    __stcs(&g_cv[p1], make_int2(c.y << 7, v.y));
    __stcs(&g_cv[p2], make_int2(c.z << 7, v.z));
    __stcs(&g_cv[p3], make_int2(c.w << 7, v.w));
}

// ---------------------------------------------------------------------------
// CSR SpMM core, quarter-warp scheme (R13 measured-best layout — unchanged).
// Lane-staged coalesced cv load + SHFL extraction; quarter q (8 lanes)
// handles edge 4g+q of each group; a lane gathers one uint4 (16B = 8 halves)
// of the edge's x row; scalar fp32 FMA accumulate in a[8].
// ---------------------------------------------------------------------------
__device__ __forceinline__ void q_accum(const char* __restrict__ xb,
                                        int ofs, float v, float* a) {
    uint4 xv = __ldg((const uint4*)(xb + ofs));
    float2 f0 = __half22float2(*(const __half2*)&xv.x);
    float2 f1 = __half22float2(*(const __half2*)&xv.y);
    float2 f2 = __half22float2(*(const __half2*)&xv.z);
    float2 f3 = __half22float2(*(const __half2*)&xv.w);
    a[0] = fmaf(v, f0.x, a[0]); a[1] = fmaf(v, f0.y, a[1]);
    a[2] = fmaf(v, f1.x, a[2]); a[3] = fmaf(v, f1.y, a[3]);
    a[4] = fmaf(v, f2.x, a[4]); a[5] = fmaf(v, f2.y, a[5]);
    a[6] = fmaf(v, f3.x, a[6]); a[7] = fmaf(v, f3.y, a[7]);
}

__device__ __forceinline__ void spmm_row(const char* __restrict__ xb,
                                         int beg, int end, int lane, float* a) {
    const int q = lane >> 3;     // quarter id: which edge of each 4-group
    int deg = end - beg;
    int full_end = beg + (deg & ~31);

    // full 32-edge chunks: 8 groups of 4 edges, branch-free
    for (int j = beg; j < full_end; j += 32) {
        int2 ed = __ldcs(g_cv + j + lane);
        #pragma unroll
        for (int g = 0; g < 8; g++) {
            int src = 4 * g + q;
            int   o = __shfl_sync(0xffffffffu, ed.x, src);
            float v = __int_as_float(__shfl_sync(0xffffffffu, ed.y, src));
            q_accum(xb, o, v, a);
        }
    }

    // partial tail chunk: predicated groups
    int m = end - full_end;
    if (m > 0) {
        int jj = full_end + lane;
        int2 ed = (jj < end) ? __ldcs(g_cv + jj) : make_int2(0, 0);
        int groups = (m + 3) >> 2;
        #pragma unroll
        for (int g = 0; g < 8; g++) {
            if (g >= groups) break;
            int src = 4 * g + q;
            int   o = __shfl_sync(0xffffffffu, ed.x, src);
            float v = __int_as_float(__shfl_sync(0xffffffffu, ed.y, src));
            bool ok = (src < m);
            q_accum(xb, ok ? o : 0, ok ? v : 0.f, a);
        }
    }

    // reduce the 4 quarter-warps (same output row, different edges)
    #pragma unroll
    for (int k = 0; k < 8; k++) {
        a[k] += __shfl_xor_sync(0xffffffffu, a[k], 8);
        a[k] += __shfl_xor_sync(0xffffffffu, a[k], 16);
    }
}

// yh = fp16(A @ x), x fp16.  40-reg cap (6 blocks/SM) — measured best.
__global__ void __launch_bounds__(256, 6) lg_csr_spmm(const __half* __restrict__ xh,
                                                      uint4* __restrict__ yh16) {
    int gtid = blockIdx.x * blockDim.x + threadIdx.x;
    int row  = gtid >> 5;
    int lane = gtid & 31;
    if (row >= N_TOTAL) return;
    int beg = __ldg(g_rowptr + row);
    int end = __ldg(g_rowptr + row + 1);
    const char* xb = (const char*)xh + (lane & 7) * 16;
    float a[8] = {0.f, 0.f, 0.f, 0.f, 0.f, 0.f, 0.f, 0.f};
    spmm_row(xb, beg, end, lane, a);
    if (lane < 8) {
        __half2 p0 = __float22half2_rn(make_float2(a[0], a[1]));
        __half2 p1 = __float22half2_rn(make_float2(a[2], a[3]));
        __half2 p2 = __float22half2_rn(make_float2(a[4], a[5]));
        __half2 p3 = __float22half2_rn(make_float2(a[6], a[7]));
        uint4 pk = make_uint4(*(unsigned*)&p0, *(unsigned*)&p1,
                              *(unsigned*)&p2, *(unsigned*)&p3);
        yh16[(size_t)row * 8 + lane] = pk;
    }
}

// Layer 3 fused with the mean: out = 0.25 * (h0 + h1 + h2 + A@h2).
// NO min-blocks clamp here (R12 showed it spills and costs ~19 us).
__global__ void __launch_bounds__(256) lg_csr_spmm_final(float* __restrict__ out) {
    int gtid = blockIdx.x * blockDim.x + threadIdx.x;
    int row  = gtid >> 5;
    int lane = gtid & 31;
    if (row >= N_TOTAL) return;
    int beg = __ldg(g_rowptr + row);
    int end = __ldg(g_rowptr + row + 1);
    const char* xb = (const char*)g_h2 + (lane & 7) * 16;
    float a[8] = {0.f, 0.f, 0.f, 0.f, 0.f, 0.f, 0.f, 0.f};
    spmm_row(xb, beg, end, lane, a);
    if (lane < 8) {
        size_t p = (size_t)row * 8 + lane;
        uint4 u0 = __ldg((const uint4*)g_h0 + p);
        uint4 u1 = __ldg((const uint4*)g_h1 + p);
        uint4 u2 = __ldg((const uint4*)g_h2 + p);
        float o[8];
        const unsigned* pu0 = &u0.x;
        const unsigned* pu1 = &u1.x;
        const unsigned* pu2 = &u2.x;
        #pragma unroll
        for (int k = 0; k < 4; k++) {
            float2 e0 = __half22float2(*(const __half2*)&pu0[k]);
            float2 e1 = __half22float2(*(const __half2*)&pu1[k]);
            float2 e2 = __half22float2(*(const __half2*)&pu2[k]);
            o[2*k]   = (e0.x + e1.x + e2.x + a[2*k])   * 0.25f;
            o[2*k+1] = (e0.y + e1.y + e2.y + a[2*k+1]) * 0.25f;
        }
        float4* dst = (float4*)(out + (size_t)row * DIM + lane * 8);
        dst[0] = make_float4(o[0], o[1], o[2], o[3]);
        dst[1] = make_float4(o[4], o[5], o[6], o[7]);
    }
}

extern "C" void kernel_launch(void* const* d_in, const int* in_sizes, int n_in,
                              void* d_out, int out_size) {
    const float* ue   = (const float*)d_in[0];
    const float* ie   = (const float*)d_in[1];
    const float* vals = (const float*)d_in[2];
    const int*   rows = (const int*)  d_in[3];
    const int*   cols = (const int*)  d_in[4];
    float* out = (float*)d_out;

    __half *h0, *h1, *h2;
    cudaGetSymbolAddress((void**)&h0, g_h0);
    cudaGetSymbolAddress((void**)&h1, g_h1);
    cudaGetSymbolAddress((void**)&h2, g_h2);

    const int TPB = 256;
    const int grid_rows = (N_TOTAL * 32 + TPB - 1) / TPB;

    lg_init_hist<<<GRID_ELEM + GRID_EDGE4, TPB>>>(ue, ie, rows);
    lg_scan     <<<NCHUNK, SCAN_CHUNK>>>();
    lg_scatter  <<<GRID_EDGE4, TPB>>>(rows, cols, vals);

    lg_csr_spmm      <<<grid_rows, TPB>>>(h0, (uint4*)h1);
    lg_csr_spmm      <<<grid_rows, TPB>>>(h1, (uint4*)h2);
    lg_csr_spmm_final<<<grid_rows, TPB>>>(out);
}

// round 17
// speedup vs baseline: 1.1785x; 1.0264x over previous
#include <cuda_runtime.h>
#include <cuda_fp16.h>
#include <cuda_bf16.h>

#define NUM_USERS 100000
#define NUM_ITEMS 50000
#define DIM 64
#define N_TOTAL (NUM_USERS + NUM_ITEMS)
#define NNZ 4800000
#define TOT (N_TOTAL * DIM)

#define SCAN_CHUNK 1024
#define NCHUNK ((N_TOTAL + SCAN_CHUNK - 1) / SCAN_CHUNK)   // 147
#define GRID_ELEM ((TOT / 4 + 255) / 256)                   // 9375
#define GRID_EDGE4 ((NNZ / 4 + 255) / 256)                  // 4688 (4 edges/thread)

// fp16 layer embeddings (gather operands AND epilogue inputs)
__device__ __align__(16) __half g_h0[TOT];
__device__ __align__(16) __half g_h1[TOT];
__device__ __align__(16) __half g_h2[TOT];

// CSR build scratch
__device__ int g_cnt[N_TOTAL];            // zero at load; re-zeroed by lg_scan each call
__device__ int g_rowptr[N_TOTAL + 1];
__device__ int g_ofs[N_TOTAL];
__device__ unsigned long long g_state[NCHUNK];  // decoupled-lookback state
__device__ __align__(8) int2 g_cv[NNZ];   // .x = row-byte-offset (col*128), .y = val bits

// ---------------------------------------------------------------------------
// fused init + hist (independent; grid-partitioned). Hist half processes
// 4 edges/thread via int4 loads (MLP=4 on the spread atomics).
// ---------------------------------------------------------------------------
__global__ void __launch_bounds__(256) lg_init_hist(const float* __restrict__ ue,
                                                    const float* __restrict__ ie,
                                                    const int* __restrict__ rows) {
    if (blockIdx.x < GRID_ELEM) {
        int i = blockIdx.x * blockDim.x + threadIdx.x;
        if (blockIdx.x == 0 && threadIdx.x < NCHUNK) g_state[threadIdx.x] = 0ULL;
        if (i >= TOT / 4) return;
        const int user4 = (NUM_USERS * DIM) / 4;
        float4 v = (i < user4) ? __ldg((const float4*)ue + i)
                               : __ldg((const float4*)ie + (i - user4));
        __half2 h01 = __float22half2_rn(make_float2(v.x, v.y));
        __half2 h23 = __float22half2_rn(make_float2(v.z, v.w));
        uint2 packed = make_uint2(*(unsigned*)&h01, *(unsigned*)&h23);
        ((uint2*)g_h0)[i] = packed;
    } else {
        int t = (blockIdx.x - GRID_ELEM) * blockDim.x + threadIdx.x;
        if (t >= NNZ / 4) return;
        int4 r = __ldcs((const int4*)rows + t);
        atomicAdd(&g_cnt[r.x], 1);
        atomicAdd(&g_cnt[r.y], 1);
        atomicAdd(&g_cnt[r.z], 1);
        atomicAdd(&g_cnt[r.w], 1);
    }
}

// ---------------------------------------------------------------------------
// Single-kernel exclusive scan (decoupled lookback, one wave on 148 SMs).
// Re-zeroes g_cnt for the next call.
// ---------------------------------------------------------------------------
__global__ void __launch_bounds__(SCAN_CHUNK) lg_scan() {
    __shared__ int ws[32];
    __shared__ int s_excl;
    const int bid = blockIdx.x;
    const int tid = threadIdx.x, lane = tid & 31, w = tid >> 5;
    const int i = bid * SCAN_CHUNK + tid;

    int v = (i < N_TOTAL) ? g_cnt[i] : 0;
    if (i < N_TOTAL) g_cnt[i] = 0;

    int inc = v;
    #pragma unroll
    for (int d = 1; d < 32; d <<= 1) {
        int t = __shfl_up_sync(0xffffffffu, inc, d);
        if (lane >= d) inc += t;
    }
    if (lane == 31) ws[w] = inc;
    __syncthreads();
    if (w == 0) {
        int s = ws[lane];
        #pragma unroll
        for (int d = 1; d < 32; d <<= 1) {
            int t = __shfl_up_sync(0xffffffffu, s, d);
            if (lane >= d) s += t;
        }
        ws[lane] = s;
    }
    __syncthreads();
    int total = ws[31];

    if (w == 0) {
        if (bid == 0) {
            if (lane == 0) {
                s_excl = 0;
                atomicExch(&g_state[0], (2ULL << 32) | (unsigned)total);
            }
        } else {
            if (lane == 0)
                atomicExch(&g_state[bid], (1ULL << 32) | (unsigned)total);
            int run = 0;
            int j = bid - 1;
            for (;;) {
                int idx = j - lane;
                unsigned long long st = (idx >= 0)
                    ? atomicAdd(&g_state[idx], 0ULL)
                    : (2ULL << 32);
                unsigned status = (unsigned)(st >> 32);
                if (__any_sync(0xffffffffu, status == 0)) continue;
                unsigned mask2 = __ballot_sync(0xffffffffu, status == 2);
                if (mask2) {
                    int firstLane = __ffs(mask2) - 1;
                    int contrib = (lane <= firstLane) ? (int)(unsigned)st : 0;
                    #pragma unroll
                    for (int d = 16; d > 0; d >>= 1)
                        contrib += __shfl_down_sync(0xffffffffu, contrib, d);
                    contrib = __shfl_sync(0xffffffffu, contrib, 0);
                    run += contrib;
                    break;
                } else {
                    int contrib = (int)(unsigned)st;
                    #pragma unroll
                    for (int d = 16; d > 0; d >>= 1)
                        contrib += __shfl_down_sync(0xffffffffu, contrib, d);
                    contrib = __shfl_sync(0xffffffffu, contrib, 0);
                    run += contrib;
                    j -= 32;
                }
            }
            if (lane == 0) {
                s_excl = run;
                atomicExch(&g_state[bid], (2ULL << 32) | (unsigned)(run + total));
            }
        }
    }
    __syncthreads();

    int excl = inc - v + (w > 0 ? ws[w - 1] : 0) + s_excl;
    if (i < N_TOTAL) { g_rowptr[i] = excl; g_ofs[i] = excl; }
    if (bid == 0 && tid == 0) g_rowptr[N_TOTAL] = NNZ;
}

// ---------------------------------------------------------------------------
// scatter: 4 edges per thread (int4 streamed loads; MLP=4 on the ATOMG+STG
// chain). cv.x stores the row BYTE OFFSET (col * 128).
// ---------------------------------------------------------------------------
__global__ void __launch_bounds__(256) lg_scatter(const int* __restrict__ rows,
                                                  const int* __restrict__ cols,
                                                  const float* __restrict__ vals) {
    int t = blockIdx.x * blockDim.x + threadIdx.x;
    if (t >= NNZ / 4) return;
    int4 r = __ldcs((const int4*)rows + t);
    int4 c = __ldcs((const int4*)cols + t);
    int4 v = __ldcs((const int4*)vals + t);   // raw fp32 bits
    int p0 = atomicAdd(&g_ofs[r.x], 1);
    int p1 = atomicAdd(&g_ofs[r.y], 1);
    int p2 = atomicAdd(&g_ofs[r.z], 1);
    int p3 = atomicAdd(&g_ofs[r.w], 1);
    __stcs(&g_cv[p0], make_int2(c.x << 7, v.x));
    __stcs(&g_cv[p1], make_int2(c.y << 7, v.y));
    __stcs(&g_cv[p2], make_int2(c.z << 7, v.z));
    __stcs(&g_cv[p3], make_int2(c.w << 7, v.w));
}

// ---------------------------------------------------------------------------
// CSR SpMM core, quarter-warp scheme (R13 measured-best layout — unchanged).
// Lane-staged coalesced cv load + SHFL extraction; quarter q (8 lanes)
// handles edge 4g+q of each group; a lane gathers one uint4 (16B = 8 halves)
// of the edge's x row; scalar fp32 FMA accumulate in a[8].
// ---------------------------------------------------------------------------
__device__ __forceinline__ void q_accum(const char* __restrict__ xb,
                                        int ofs, float v, float* a) {
    uint4 xv = __ldg((const uint4*)(xb + ofs));
    float2 f0 = __half22float2(*(const __half2*)&xv.x);
    float2 f1 = __half22float2(*(const __half2*)&xv.y);
    float2 f2 = __half22float2(*(const __half2*)&xv.z);
    float2 f3 = __half22float2(*(const __half2*)&xv.w);
    a[0] = fmaf(v, f0.x, a[0]); a[1] = fmaf(v, f0.y, a[1]);
    a[2] = fmaf(v, f1.x, a[2]); a[3] = fmaf(v, f1.y, a[3]);
    a[4] = fmaf(v, f2.x, a[4]); a[5] = fmaf(v, f2.y, a[5]);
    a[6] = fmaf(v, f3.x, a[6]); a[7] = fmaf(v, f3.y, a[7]);
}

__device__ __forceinline__ void spmm_row(const char* __restrict__ xb,
                                         int beg, int end, int lane, float* a) {
    const int q = lane >> 3;     // quarter id: which edge of each 4-group
    int deg = end - beg;
    int full_end = beg + (deg & ~31);

    // full 32-edge chunks: 8 groups of 4 edges, branch-free
    for (int j = beg; j < full_end; j += 32) {
        int2 ed = __ldcs(g_cv + j + lane);
        #pragma unroll
        for (int g = 0; g < 8; g++) {
            int src = 4 * g + q;
            int   o = __shfl_sync(0xffffffffu, ed.x, src);
            float v = __int_as_float(__shfl_sync(0xffffffffu, ed.y, src));
            q_accum(xb, o, v, a);
        }
    }

    // partial tail chunk: predicated groups
    int m = end - full_end;
    if (m > 0) {
        int jj = full_end + lane;
        int2 ed = (jj < end) ? __ldcs(g_cv + jj) : make_int2(0, 0);
        int groups = (m + 3) >> 2;
        #pragma unroll
        for (int g = 0; g < 8; g++) {
            if (g >= groups) break;
            int src = 4 * g + q;
            int   o = __shfl_sync(0xffffffffu, ed.x, src);
            float v = __int_as_float(__shfl_sync(0xffffffffu, ed.y, src));
            bool ok = (src < m);
            q_accum(xb, ok ? o : 0, ok ? v : 0.f, a);
        }
    }

    // reduce the 4 quarter-warps (same output row, different edges)
    #pragma unroll
    for (int k = 0; k < 8; k++) {
        a[k] += __shfl_xor_sync(0xffffffffu, a[k], 8);
        a[k] += __shfl_xor_sync(0xffffffffu, a[k], 16);
    }
}

// yh = fp16(A @ x), x fp16.  TPB=128, 12 blocks/SM (same 40-reg cap, same
// 48 warps/SM as the 256/6 config, but half the per-block work variance —
// targets the occ 63% vs 75% tail gap).
__global__ void __launch_bounds__(128, 12) lg_csr_spmm(const __half* __restrict__ xh,
                                                       uint4* __restrict__ yh16) {
    int gtid = blockIdx.x * blockDim.x + threadIdx.x;
    int row  = gtid >> 5;
    int lane = gtid & 31;
    if (row >= N_TOTAL) return;
    int beg = __ldg(g_rowptr + row);
    int end = __ldg(g_rowptr + row + 1);
    const char* xb = (const char*)xh + (lane & 7) * 16;
    float a[8] = {0.f, 0.f, 0.f, 0.f, 0.f, 0.f, 0.f, 0.f};
    spmm_row(xb, beg, end, lane, a);
    if (lane < 8) {
        __half2 p0 = __float22half2_rn(make_float2(a[0], a[1]));
        __half2 p1 = __float22half2_rn(make_float2(a[2], a[3]));
        __half2 p2 = __float22half2_rn(make_float2(a[4], a[5]));
        __half2 p3 = __float22half2_rn(make_float2(a[6], a[7]));
        uint4 pk = make_uint4(*(unsigned*)&p0, *(unsigned*)&p1,
                              *(unsigned*)&p2, *(unsigned*)&p3);
        yh16[(size_t)row * 8 + lane] = pk;
    }
}

// Layer 3 fused with the mean: out = 0.25 * (h0 + h1 + h2 + A@h2).
// TPB=128, NO min-blocks clamp (R12 showed a reg cap here spills).
__global__ void __launch_bounds__(128) lg_csr_spmm_final(float* __restrict__ out) {
    int gtid = blockIdx.x * blockDim.x + threadIdx.x;
    int row  = gtid >> 5;
    int lane = gtid & 31;
    if (row >= N_TOTAL) return;
    int beg = __ldg(g_rowptr + row);
    int end = __ldg(g_rowptr + row + 1);
    const char* xb = (const char*)g_h2 + (lane & 7) * 16;
    float a[8] = {0.f, 0.f, 0.f, 0.f, 0.f, 0.f, 0.f, 0.f};
    spmm_row(xb, beg, end, lane, a);
    if (lane < 8) {
        size_t p = (size_t)row * 8 + lane;
        uint4 u0 = __ldg((const uint4*)g_h0 + p);
        uint4 u1 = __ldg((const uint4*)g_h1 + p);
        uint4 u2 = __ldg((const uint4*)g_h2 + p);
        float o[8];
        const unsigned* pu0 = &u0.x;
        const unsigned* pu1 = &u1.x;
        const unsigned* pu2 = &u2.x;
        #pragma unroll
        for (int k = 0; k < 4; k++) {
            float2 e0 = __half22float2(*(const __half2*)&pu0[k]);
            float2 e1 = __half22float2(*(const __half2*)&pu1[k]);
            float2 e2 = __half22float2(*(const __half2*)&pu2[k]);
            o[2*k]   = (e0.x + e1.x + e2.x + a[2*k])   * 0.25f;
            o[2*k+1] = (e0.y + e1.y + e2.y + a[2*k+1]) * 0.25f;
        }
        float4* dst = (float4*)(out + (size_t)row * DIM + lane * 8);
        dst[0] = make_float4(o[0], o[1], o[2], o[3]);
        dst[1] = make_float4(o[4], o[5], o[6], o[7]);
    }
}

extern "C" void kernel_launch(void* const* d_in, const int* in_sizes, int n_in,
                              void* d_out, int out_size) {
    const float* ue   = (const float*)d_in[0];
    const float* ie   = (const float*)d_in[1];
    const float* vals = (const float*)d_in[2];
    const int*   rows = (const int*)  d_in[3];
    const int*   cols = (const int*)  d_in[4];
    float* out = (float*)d_out;

    __half *h0, *h1, *h2;
    cudaGetSymbolAddress((void**)&h0, g_h0);
    cudaGetSymbolAddress((void**)&h1, g_h1);
    cudaGetSymbolAddress((void**)&h2, g_h2);

    const int TPB = 256;
    const int TPB_SPMM = 128;
    const int grid_rows = (N_TOTAL * 32 + TPB_SPMM - 1) / TPB_SPMM;  // 37500

    lg_init_hist<<<GRID_ELEM + GRID_EDGE4, TPB>>>(ue, ie, rows);
    lg_scan     <<<NCHUNK, SCAN_CHUNK>>>();
    lg_scatter  <<<GRID_EDGE4, TPB>>>(rows, cols, vals);

    lg_csr_spmm      <<<grid_rows, TPB_SPMM>>>(h0, (uint4*)h1);
    lg_csr_spmm      <<<grid_rows, TPB_SPMM>>>(h1, (uint4*)h2);
    lg_csr_spmm_final<<<grid_rows, TPB_SPMM>>>(out);
}